// round 4
// baseline (speedup 1.0000x reference)
#include <cuda_runtime.h>

#define LATENTS 128
#define HIDDEN  256
#define TM      32
#define NTHR    512
#define TSTEPS  100
#define NROWS   4096

typedef unsigned long long ULL;

// k-pair-packed weights, built once per launch by pack_weights_kernel.
__device__ float W1p_g[64 * HIDDEN * 2];    // ULL view: [64][256], (W1[2j][c],W1[2j+1][c])
__device__ float W2p_g[128 * LATENTS * 2];  // ULL view: [128][128]

__device__ __forceinline__ ULL ffma2(ULL a, ULL b, ULL c) {
    ULL d; asm("fma.rn.f32x2 %0, %1, %2, %3;" : "=l"(d) : "l"(a), "l"(b), "l"(c)); return d;
}
__device__ __forceinline__ ULL pack2(float x) {
    ULL d; asm("mov.b64 %0, {%1, %1};" : "=l"(d) : "f"(x)); return d;
}
__device__ __forceinline__ ULL packab(float a, float b) {
    ULL d; asm("mov.b64 %0, {%1, %2};" : "=l"(d) : "f"(a), "f"(b)); return d;
}
__device__ __forceinline__ void unpack2(ULL v, float& lo, float& hi) {
    asm("mov.b64 {%0, %1}, %2;" : "=f"(lo), "=f"(hi) : "l"(v));
}
__device__ __forceinline__ float fast_tanh(float x) {
    float e = __expf(2.0f * x);
    return 1.0f - __fdividef(2.0f, e + 1.0f);
}
__device__ __forceinline__ unsigned smem_u32(const void* p) {
    return (unsigned)__cvta_generic_to_shared(p);
}
__device__ __forceinline__ void cp16(unsigned dst, const float* src) {
    asm volatile("cp.async.cg.shared.global [%0], [%1], 16;" :: "r"(dst), "l"(src) : "memory");
}

__global__ void pack_weights_kernel(const float* __restrict__ W1,
                                    const float* __restrict__ W2) {
    int i = blockIdx.x * blockDim.x + threadIdx.x;   // 16384 threads
    int j1 = i >> 8, c1 = i & 255;
    ((float2*)W1p_g)[i] = make_float2(W1[(2 * j1) * HIDDEN + c1],
                                      W1[(2 * j1 + 1) * HIDDEN + c1]);
    int j2 = i >> 7, c2 = i & 127;
    ((float2*)W2p_g)[i] = make_float2(W2[(2 * j2) * LATENTS + c2],
                                      W2[(2 * j2 + 1) * LATENTS + c2]);
}

// smem: W1u [0,131072) ULL[64][256]
//       Ys  [131072,147456) float[32][128]
//       Zs  [147456,180224) float[32][256]
//       W2t [180224,212992) 2 x 16KB tile buffers (ULL[16][128] each)
#define SM_BYTES 212992

__global__ __launch_bounds__(NTHR, 1)
void ode_rk4_kernel(const float* __restrict__ fp,
                    const float* __restrict__ ts,
                    const float* __restrict__ b1,
                    const float* __restrict__ b2,
                    float* __restrict__ out)
{
    extern __shared__ char smraw[];
    ULL*   W1u = (ULL*)smraw;
    float* Ys  = (float*)(smraw + 131072);
    float* Zs  = (float*)(smraw + 147456);
    float* W2t = (float*)(smraw + 180224);

    const int tid = threadIdx.x;
    const int tc  = tid & 31;
    const int w   = tid >> 5;
    const int wr  = w >> 2;               // GEMM1 rows 8wr..8wr+7
    const int wc  = w & 3;
    const int c1  = 64 * wc + 2 * tc;     // GEMM1 cols c1, c1+1
    const int rg  = w >> 1;               // GEMM2 (w<8) rows 8rg..8rg+7
    const int cb  = w & 1;
    const int c2  = 64 * cb + 2 * tc;     // GEMM2 cols c2, c2+1
    const bool cw = (w < 8);
    const int row0 = blockIdx.x * TM;

    for (int i = tid; i < 32768 / 4; i += NTHR)
        ((float4*)W1u)[i] = ((const float4*)W1p_g)[i];

    for (int i = tid; i < TM * LATENTS / 4; i += NTHR) {
        int r = i >> 5, c4 = i & 31;
        float4 v = ((const float4*)(fp + (size_t)(row0 + r) * LATENTS))[c4];
        ((float4*)(out + (size_t)(row0 + r) * TSTEPS * LATENTS))[c4] = v;
    }

    const ULL rb1a = packab(b1[c1], 0.f);
    const ULL rb1b = packab(b1[c1 + 1], 0.f);

    ULL yb[8], acc[8], rb2a = 0, rb2b = 0;
    if (cw) {
        rb2a = packab(b2[c2], 0.f);
        rb2b = packab(b2[c2 + 1], 0.f);
        #pragma unroll
        for (int r = 0; r < 8; r++) {
            yb[r] = *(const ULL*)&fp[(size_t)(row0 + 8 * rg + r) * LATENTS + c2];
            *(ULL*)&Ys[(8 * rg + r) * LATENTS + c2] = yb[r];
        }
    }
    __syncthreads();

    const int li = (w - 8) * 32 + tc;              // copy-warp linear id 0..255
    const unsigned W2t_u32 = smem_u32(W2t);

    for (int t = 0; t < TSTEPS - 1; t++) {
        float dt   = __ldg(&ts[t + 1]) - __ldg(&ts[t]);
        float half = 0.5f * dt;

        #pragma unroll 1
        for (int s = 0; s < 4; s++) {
            // Copy warps: kick tile 0 into buf0 (completes during GEMM1).
            if (!cw) {
                #pragma unroll
                for (int n = 0; n < 4; n++)
                    cp16(W2t_u32 + (unsigned)(li * 4 + n * 1024) * 4,
                         W2p_g + li * 4 + n * 1024);
                asm volatile("cp.async.commit_group;" ::: "memory");
            }

            // ---------------- GEMM1 (all 16 warps, k-pair packed) ----------
            ULL hp[8][2];
            #pragma unroll
            for (int r = 0; r < 8; r++) { hp[r][0] = rb1a; hp[r][1] = rb1b; }
            {
                const float* yrow = Ys + 8 * wr * LATENTS;
                #pragma unroll 2
                for (int j = 0; j < 64; j += 2) {
                    ulonglong2 wA = *(const ulonglong2*)&W1u[j * HIDDEN + c1];
                    ulonglong2 wB = *(const ulonglong2*)&W1u[(j + 1) * HIDDEN + c1];
                    #pragma unroll
                    for (int r = 0; r < 8; r++) {
                        ulonglong2 yv = *(const ulonglong2*)&yrow[r * LATENTS + 2 * j];
                        hp[r][0] = ffma2(yv.x, wA.x, hp[r][0]);
                        hp[r][1] = ffma2(yv.x, wA.y, hp[r][1]);
                        hp[r][0] = ffma2(yv.y, wB.x, hp[r][0]);
                        hp[r][1] = ffma2(yv.y, wB.y, hp[r][1]);
                    }
                }
            }

            // tanh(lo+hi) -> Zs
            #pragma unroll
            for (int r = 0; r < 8; r++) {
                float a0, a1, e0, e1;
                unpack2(hp[r][0], a0, a1);
                unpack2(hp[r][1], e0, e1);
                *(ULL*)&Zs[(8 * wr + r) * HIDDEN + c1] =
                    packab(fast_tanh(a0 + a1), fast_tanh(e0 + e1));
            }
            __syncthreads();

            // ---------------- GEMM2 (warps 0-7 compute, 8-15 cp.async) -----
            ULL op[8][2];
            #pragma unroll
            for (int r = 0; r < 8; r++) { op[r][0] = rb2a; op[r][1] = rb2b; }

            #pragma unroll 1
            for (int kt = 0; kt < 8; kt++) {
                if (!cw) asm volatile("cp.async.wait_group 0;" ::: "memory");
                __syncthreads();
                if (!cw) {
                    if (kt < 7) {
                        const float* src = W2p_g + (kt + 1) * 4096 + li * 4;
                        unsigned dst = W2t_u32 +
                            (unsigned)(((kt + 1) & 1) * 4096 + li * 4) * 4;
                        #pragma unroll
                        for (int n = 0; n < 4; n++)
                            cp16(dst + n * 4096, src + n * 1024);
                        asm volatile("cp.async.commit_group;" ::: "memory");
                    }
                } else {
                    const ULL*   Wt   = (const ULL*)(W2t + (kt & 1) * 4096);
                    const float* zrow = Zs + 8 * rg * HIDDEN + 32 * kt;
                    #pragma unroll 2
                    for (int j = 0; j < 16; j += 2) {
                        ulonglong2 wA = *(const ulonglong2*)&Wt[j * LATENTS + c2];
                        ulonglong2 wB = *(const ulonglong2*)&Wt[(j + 1) * LATENTS + c2];
                        #pragma unroll
                        for (int r = 0; r < 8; r++) {
                            ulonglong2 zv = *(const ulonglong2*)&zrow[r * HIDDEN + 2 * j];
                            op[r][0] = ffma2(zv.x, wA.x, op[r][0]);
                            op[r][1] = ffma2(zv.x, wA.y, op[r][1]);
                            op[r][0] = ffma2(zv.y, wB.x, op[r][0]);
                            op[r][1] = ffma2(zv.y, wB.y, op[r][1]);
                        }
                    }
                }
            }

            // ---------------- RK4 epilogue (warps 0-7, col-pair packed) ----
            if (cw) {
                ULL oU[8];
                #pragma unroll
                for (int r = 0; r < 8; r++) {
                    float o0, o1, p0, p1;
                    unpack2(op[r][0], o0, o1);
                    unpack2(op[r][1], p0, p1);
                    oU[r] = packab(o0 + o1, p0 + p1);
                }
                if (s == 0) {
                    #pragma unroll
                    for (int r = 0; r < 8; r++) acc[r] = oU[r];
                } else {
                    ULL cwv = pack2((s == 3) ? 1.0f : 2.0f);
                    #pragma unroll
                    for (int r = 0; r < 8; r++) acc[r] = ffma2(cwv, oU[r], acc[r]);
                }
                if (s < 3) {
                    ULL ew = pack2((s < 2) ? half : dt);
                    #pragma unroll
                    for (int r = 0; r < 8; r++)
                        *(ULL*)&Ys[(8 * rg + r) * LATENTS + c2] = ffma2(ew, oU[r], yb[r]);
                } else {
                    ULL c6 = pack2(dt * (1.0f / 6.0f));
                    #pragma unroll
                    for (int r = 0; r < 8; r++) {
                        yb[r] = ffma2(c6, acc[r], yb[r]);
                        *(ULL*)&Ys[(8 * rg + r) * LATENTS + c2] = yb[r];
                        *(ULL*)&out[((size_t)(row0 + 8 * rg + r) * TSTEPS + (t + 1)) * LATENTS + c2] = yb[r];
                    }
                }
            }
            __syncthreads();
        }
    }
}

extern "C" void kernel_launch(void* const* d_in, const int* in_sizes, int n_in,
                              void* d_out, int out_size) {
    const float* fp = (const float*)d_in[0];
    const float* ts = (const float*)d_in[1];
    const float* W1 = (const float*)d_in[2];
    const float* b1 = (const float*)d_in[3];
    const float* W2 = (const float*)d_in[4];
    const float* b2 = (const float*)d_in[5];
    float* out = (float*)d_out;

    pack_weights_kernel<<<64, 256>>>(W1, W2);

    cudaFuncSetAttribute(ode_rk4_kernel,
                         cudaFuncAttributeMaxDynamicSharedMemorySize, SM_BYTES);
    ode_rk4_kernel<<<NROWS / TM, NTHR, SM_BYTES>>>(fp, ts, b1, b2, out);
}

// round 8
// speedup vs baseline: 1.1230x; 1.1230x over previous
#include <cuda_runtime.h>

#define LATENTS 128
#define HIDDEN  256
#define TM      32
#define NTHR    512
#define TSTEPS  100
#define NROWS   4096

typedef unsigned long long ULL;

__device__ __forceinline__ ULL ffma2(ULL a, ULL b, ULL c) {
    ULL d; asm("fma.rn.f32x2 %0, %1, %2, %3;" : "=l"(d) : "l"(a), "l"(b), "l"(c)); return d;
}
__device__ __forceinline__ ULL pack2(float x) {
    ULL d; asm("mov.b64 %0, {%1, %1};" : "=l"(d) : "f"(x)); return d;
}
__device__ __forceinline__ ULL packab(float a, float b) {
    ULL d; asm("mov.b64 %0, {%1, %2};" : "=l"(d) : "f"(a), "f"(b)); return d;
}
__device__ __forceinline__ void unpack2(ULL v, float& lo, float& hi) {
    asm("mov.b64 {%0, %1}, %2;" : "=f"(lo), "=f"(hi) : "l"(v));
}
__device__ __forceinline__ float fast_tanh(float x) {
    float e = __expf(2.0f * x);
    return 1.0f - __fdividef(2.0f, e + 1.0f);
}
__device__ __forceinline__ void cp16(unsigned dst, const float* src) {
    asm volatile("cp.async.cg.shared.global [%0], [%1], 16;" :: "r"(dst), "l"(src) : "memory");
}
__device__ __forceinline__ void cp_commit() {
    asm volatile("cp.async.commit_group;" ::: "memory");
}
__device__ __forceinline__ void cp_wait1() {
    asm volatile("cp.async.wait_group 1;" ::: "memory");
}

// smem (bytes): W1s [0,131072) fp32[128][256]
//               Yp  [131072,147456) ULL[16][128]   row-pair state
//               Zp  [147456,180224) ULL[16][256]   row-pair tanh acts
//               W2t [180224,229376) 3 x 16KB tile buffers (fp32[32][128] each)
#define SM_BYTES 229376

__global__ __launch_bounds__(NTHR, 1)
void ode_rk4_kernel(const float* __restrict__ fp,
                    const float* __restrict__ ts,
                    const float* __restrict__ W1,
                    const float* __restrict__ b1,
                    const float* __restrict__ W2,
                    const float* __restrict__ b2,
                    float* __restrict__ out)
{
    extern __shared__ char smraw[];
    float* W1s = (float*)smraw;
    ULL*   Yp  = (ULL*)(smraw + 131072);
    ULL*   Zp  = (ULL*)(smraw + 147456);
    float* W2t = (float*)(smraw + 180224);

    const int tid = threadIdx.x;
    const int tc  = tid & 31;
    const int w   = tid >> 5;
    const int wr  = w >> 2;          // GEMM1 row group: pairs 4wr..4wr+3
    const int wc  = w & 3;           // GEMM1 col block: 64wc
    const int rg  = w >> 1;          // GEMM2 (w<8): pairs 4rg..4rg+3
    const int wc2 = w & 1;           // GEMM2 col block: 64wc2
    const bool compute_w = (w < 8);
    const int row0 = blockIdx.x * TM;

    unsigned smem_base;
    asm("{ .reg .u64 t; cvta.to.shared.u64 t, %1; cvt.u32.u64 %0, t; }"
        : "=r"(smem_base) : "l"(smraw));
    const unsigned W2t_u = smem_base + 180224;
    const int li = tid - 256;                      // copy-thread id 0..255

    // Stage W1 (coalesced float4).
    for (int i = tid; i < LATENTS * HIDDEN / 4; i += NTHR)
        ((float4*)W1s)[i] = ((const float4*)W1)[i];

    // t=0 output, fully coalesced.
    for (int i = tid; i < TM * LATENTS / 4; i += NTHR) {
        int r = i >> 5, c4 = i & 31;
        float4 v = ((const float4*)(fp + (size_t)(row0 + r) * LATENTS))[c4];
        ((float4*)(out + (size_t)(row0 + r) * TSTEPS * LATENTS))[c4] = v;
    }

    const ULL rb1lo = pack2(b1[64 * wc + 2 * tc]);
    const ULL rb1hi = pack2(b1[64 * wc + 2 * tc + 1]);

    ULL yb[4][2], acc[4][2], rb2[2];
    const int cb = 64 * wc2 + 2 * tc;
    if (compute_w) {
        rb2[0] = pack2(b2[cb]);
        rb2[1] = pack2(b2[cb + 1]);
        #pragma unroll
        for (int p = 0; p < 4; p++) {
            int r = row0 + 8 * rg + 2 * p;
            yb[p][0] = packab(fp[(size_t)r * LATENTS + cb],     fp[(size_t)(r + 1) * LATENTS + cb]);
            yb[p][1] = packab(fp[(size_t)r * LATENTS + cb + 1], fp[(size_t)(r + 1) * LATENTS + cb + 1]);
            ulonglong2 yy; yy.x = yb[p][0]; yy.y = yb[p][1];
            *(ulonglong2*)&Yp[(4 * rg + p) * LATENTS + cb] = yy;
        }
    }
    __syncthreads();

    for (int t = 0; t < TSTEPS - 1; t++) {
        float dt   = __ldg(&ts[t + 1]) - __ldg(&ts[t]);
        float half = 0.5f * dt;

        #pragma unroll 1
        for (int s = 0; s < 4; s++) {
            // Copy warps: async-commit tiles 0 and 1 (land during GEMM1).
            if (!compute_w) {
                const float* s0 = W2 + li * 16;
                unsigned d0 = W2t_u + (unsigned)li * 64;
                cp16(d0,      s0);     cp16(d0 + 16, s0 + 4);
                cp16(d0 + 32, s0 + 8); cp16(d0 + 48, s0 + 12);
                cp_commit();
                const float* s1 = s0 + 4096;
                unsigned d1 = d0 + 16384;
                cp16(d1,      s1);     cp16(d1 + 16, s1 + 4);
                cp16(d1 + 32, s1 + 8); cp16(d1 + 48, s1 + 12);
                cp_commit();
            }

            // ---------------- GEMM1 (all 16 warps, row-pair) ----------------
            ULL h[4][2];
            #pragma unroll
            for (int p = 0; p < 4; p++) { h[p][0] = rb1lo; h[p][1] = rb1hi; }
            {
                const float* w1c = &W1s[64 * wc + 2 * tc];
                const ULL*   yp0 = &Yp[(4 * wr + 0) * LATENTS];
                const ULL*   yp1 = &Yp[(4 * wr + 1) * LATENTS];
                const ULL*   yp2 = &Yp[(4 * wr + 2) * LATENTS];
                const ULL*   yp3 = &Yp[(4 * wr + 3) * LATENTS];
                #pragma unroll 2
                for (int k0 = 0; k0 < LATENTS; k0 += 2) {
                    ulonglong2 a0 = *(const ulonglong2*)&yp0[k0];
                    ulonglong2 a1 = *(const ulonglong2*)&yp1[k0];
                    ulonglong2 a2 = *(const ulonglong2*)&yp2[k0];
                    ulonglong2 a3 = *(const ulonglong2*)&yp3[k0];
                    ULL wv0 = *(const ULL*)&w1c[(k0    ) * HIDDEN];
                    ULL wv1 = *(const ULL*)&w1c[(k0 + 1) * HIDDEN];
                    float wl, wh;
                    unpack2(wv0, wl, wh);
                    { ULL bl = pack2(wl), bh = pack2(wh);
                      h[0][0] = ffma2(a0.x, bl, h[0][0]); h[0][1] = ffma2(a0.x, bh, h[0][1]);
                      h[1][0] = ffma2(a1.x, bl, h[1][0]); h[1][1] = ffma2(a1.x, bh, h[1][1]);
                      h[2][0] = ffma2(a2.x, bl, h[2][0]); h[2][1] = ffma2(a2.x, bh, h[2][1]);
                      h[3][0] = ffma2(a3.x, bl, h[3][0]); h[3][1] = ffma2(a3.x, bh, h[3][1]); }
                    unpack2(wv1, wl, wh);
                    { ULL bl = pack2(wl), bh = pack2(wh);
                      h[0][0] = ffma2(a0.y, bl, h[0][0]); h[0][1] = ffma2(a0.y, bh, h[0][1]);
                      h[1][0] = ffma2(a1.y, bl, h[1][0]); h[1][1] = ffma2(a1.y, bh, h[1][1]);
                      h[2][0] = ffma2(a2.y, bl, h[2][0]); h[2][1] = ffma2(a2.y, bh, h[2][1]);
                      h[3][0] = ffma2(a3.y, bl, h[3][0]); h[3][1] = ffma2(a3.y, bh, h[3][1]); }
                }
            }

            // tanh -> Zp (dense STS.128, conflict-free).
            #pragma unroll
            for (int p = 0; p < 4; p++) {
                float x0, x1, x2, x3;
                unpack2(h[p][0], x0, x1);
                unpack2(h[p][1], x2, x3);
                ulonglong2 zz;
                zz.x = packab(fast_tanh(x0), fast_tanh(x1));
                zz.y = packab(fast_tanh(x2), fast_tanh(x3));
                *(ulonglong2*)&Zp[(4 * wr + p) * HIDDEN + 64 * wc + 2 * tc] = zz;
            }
            __syncthreads();

            // ---------------- GEMM2 (warps 0-7 compute, 8-15 cp.async) ------
            ULL o[4][2];
            if (compute_w) {
                #pragma unroll
                for (int p = 0; p < 4; p++) { o[p][0] = rb2[0]; o[p][1] = rb2[1]; }
            }

            #pragma unroll 1
            for (int kt = 0; kt < 8; kt++) {
                if (!compute_w) cp_wait1();        // tile kt landed
                __syncthreads();                   // tile kt visible to all
                if (!compute_w) {
                    if (kt < 6) {
                        const float* src = W2 + (kt + 2) * 4096 + li * 16;
                        unsigned dst = W2t_u + (unsigned)(((kt + 2) % 3) * 16384 + li * 64);
                        cp16(dst,      src);     cp16(dst + 16, src + 4);
                        cp16(dst + 32, src + 8); cp16(dst + 48, src + 12);
                        cp_commit();
                    }
                } else {
                    const float* Wt = W2t + (kt % 3) * 4096 + cb;
                    const ULL* zb0 = &Zp[(4 * rg + 0) * HIDDEN + kt * 32];
                    const ULL* zb1 = &Zp[(4 * rg + 1) * HIDDEN + kt * 32];
                    const ULL* zb2 = &Zp[(4 * rg + 2) * HIDDEN + kt * 32];
                    const ULL* zb3 = &Zp[(4 * rg + 3) * HIDDEN + kt * 32];
                    #pragma unroll 4
                    for (int kk0 = 0; kk0 < 32; kk0 += 2) {
                        ulonglong2 z0 = *(const ulonglong2*)&zb0[kk0];
                        ulonglong2 z1 = *(const ulonglong2*)&zb1[kk0];
                        ulonglong2 z2 = *(const ulonglong2*)&zb2[kk0];
                        ulonglong2 z3 = *(const ulonglong2*)&zb3[kk0];
                        ULL wv0 = *(const ULL*)&Wt[(kk0    ) * LATENTS];
                        ULL wv1 = *(const ULL*)&Wt[(kk0 + 1) * LATENTS];
                        float wl, wh;
                        unpack2(wv0, wl, wh);
                        { ULL bl = pack2(wl), bh = pack2(wh);
                          o[0][0] = ffma2(z0.x, bl, o[0][0]); o[0][1] = ffma2(z0.x, bh, o[0][1]);
                          o[1][0] = ffma2(z1.x, bl, o[1][0]); o[1][1] = ffma2(z1.x, bh, o[1][1]);
                          o[2][0] = ffma2(z2.x, bl, o[2][0]); o[2][1] = ffma2(z2.x, bh, o[2][1]);
                          o[3][0] = ffma2(z3.x, bl, o[3][0]); o[3][1] = ffma2(z3.x, bh, o[3][1]); }
                        unpack2(wv1, wl, wh);
                        { ULL bl = pack2(wl), bh = pack2(wh);
                          o[0][0] = ffma2(z0.y, bl, o[0][0]); o[0][1] = ffma2(z0.y, bh, o[0][1]);
                          o[1][0] = ffma2(z1.y, bl, o[1][0]); o[1][1] = ffma2(z1.y, bh, o[1][1]);
                          o[2][0] = ffma2(z2.y, bl, o[2][0]); o[2][1] = ffma2(z2.y, bh, o[2][1]);
                          o[3][0] = ffma2(z3.y, bl, o[3][0]); o[3][1] = ffma2(z3.y, bh, o[3][1]); }
                    }
                }
            }

            // ---------------- RK4 epilogue (packed, warps 0-7) --------------
            if (compute_w) {
                if (s == 0) {
                    #pragma unroll
                    for (int p = 0; p < 4; p++) { acc[p][0] = o[p][0]; acc[p][1] = o[p][1]; }
                } else {
                    ULL cwv = pack2((s == 3) ? 1.0f : 2.0f);
                    #pragma unroll
                    for (int p = 0; p < 4; p++) {
                        acc[p][0] = ffma2(cwv, o[p][0], acc[p][0]);
                        acc[p][1] = ffma2(cwv, o[p][1], acc[p][1]);
                    }
                }
                if (s < 3) {
                    ULL ewv = pack2((s < 2) ? half : dt);
                    #pragma unroll
                    for (int p = 0; p < 4; p++) {
                        ulonglong2 yy;
                        yy.x = ffma2(ewv, o[p][0], yb[p][0]);
                        yy.y = ffma2(ewv, o[p][1], yb[p][1]);
                        *(ulonglong2*)&Yp[(4 * rg + p) * LATENTS + cb] = yy;
                    }
                } else {
                    ULL c6 = pack2(dt * (1.0f / 6.0f));
                    #pragma unroll
                    for (int p = 0; p < 4; p++) {
                        yb[p][0] = ffma2(c6, acc[p][0], yb[p][0]);
                        yb[p][1] = ffma2(c6, acc[p][1], yb[p][1]);
                        ulonglong2 yy; yy.x = yb[p][0]; yy.y = yb[p][1];
                        *(ulonglong2*)&Yp[(4 * rg + p) * LATENTS + cb] = yy;
                        int r = row0 + 8 * rg + 2 * p;
                        float lo, hi;
                        size_t base0 = ((size_t)r * TSTEPS + (t + 1)) * LATENTS + cb;
                        size_t base1 = ((size_t)(r + 1) * TSTEPS + (t + 1)) * LATENTS + cb;
                        unpack2(yb[p][0], lo, hi);
                        out[base0] = lo;     out[base1] = hi;
                        unpack2(yb[p][1], lo, hi);
                        out[base0 + 1] = lo; out[base1 + 1] = hi;
                    }
                }
            }
            __syncthreads();
        }
    }
}

extern "C" void kernel_launch(void* const* d_in, const int* in_sizes, int n_in,
                              void* d_out, int out_size) {
    const float* fp = (const float*)d_in[0];
    const float* ts = (const float*)d_in[1];
    const float* W1 = (const float*)d_in[2];
    const float* b1 = (const float*)d_in[3];
    const float* W2 = (const float*)d_in[4];
    const float* b2 = (const float*)d_in[5];
    float* out = (float*)d_out;

    cudaFuncSetAttribute(ode_rk4_kernel,
                         cudaFuncAttributeMaxDynamicSharedMemorySize, SM_BYTES);
    ode_rk4_kernel<<<NROWS / TM, NTHR, SM_BYTES>>>(fp, ts, W1, b1, W2, b2, out);
}

// round 9
// speedup vs baseline: 1.1941x; 1.0633x over previous
#include <cuda_runtime.h>

#define LATENTS 128
#define HIDDEN  256
#define TM      32
#define NTHR    512
#define TSTEPS  100
#define NROWS   4096

typedef unsigned long long ULL;

__device__ __forceinline__ ULL ffma2(ULL a, ULL b, ULL c) {
    ULL d; asm("fma.rn.f32x2 %0, %1, %2, %3;" : "=l"(d) : "l"(a), "l"(b), "l"(c)); return d;
}
__device__ __forceinline__ ULL pack2(float x) {
    ULL d; asm("mov.b64 %0, {%1, %1};" : "=l"(d) : "f"(x)); return d;
}
__device__ __forceinline__ ULL packab(float a, float b) {
    ULL d; asm("mov.b64 %0, {%1, %2};" : "=l"(d) : "f"(a), "f"(b)); return d;
}
__device__ __forceinline__ void unpack2(ULL v, float& lo, float& hi) {
    asm("mov.b64 {%0, %1}, %2;" : "=f"(lo), "=f"(hi) : "l"(v));
}
__device__ __forceinline__ float fast_tanh(float x) {
    float e = __expf(2.0f * x);
    return 1.0f - __fdividef(2.0f, e + 1.0f);
}
__device__ __forceinline__ void cp16(unsigned dst, const float* src) {
    asm volatile("cp.async.cg.shared.global [%0], [%1], 16;" :: "r"(dst), "l"(src) : "memory");
}
__device__ __forceinline__ void cp_commit() {
    asm volatile("cp.async.commit_group;" ::: "memory");
}
__device__ __forceinline__ void cp_wait1() {
    asm volatile("cp.async.wait_group 1;" ::: "memory");
}

// smem (bytes): W1s [0,131072) fp32[128][256]
//               Yp  [131072,147456) ULL[16][128]   row-pair state
//               Zp  [147456,180224) ULL[16][256]   row-pair tanh acts
//               W2t [180224,229376) 3 x 16KB tile buffers (fp32[32][128] each)
//               Red = W2t buf0 region (reused after tile 6 is consumed)
#define SM_BYTES 229376

__global__ __launch_bounds__(NTHR, 1)
void ode_rk4_kernel(const float* __restrict__ fp,
                    const float* __restrict__ ts,
                    const float* __restrict__ W1,
                    const float* __restrict__ b1,
                    const float* __restrict__ W2,
                    const float* __restrict__ b2,
                    float* __restrict__ out)
{
    extern __shared__ char smraw[];
    float* W1s = (float*)smraw;
    ULL*   Yp  = (ULL*)(smraw + 131072);
    ULL*   Zp  = (ULL*)(smraw + 147456);
    float* W2t = (float*)(smraw + 180224);
    ULL*   Red = (ULL*)(smraw + 180224);      // aliases buf0; used post-loop only

    const int tid = threadIdx.x;
    const int tc  = tid & 31;
    const int w   = tid >> 5;
    const int wr  = w >> 2;          // GEMM1 row group: pairs 4wr..4wr+3
    const int wc  = w & 3;           // GEMM1 col block: 64wc
    const int rg  = (w & 7) >> 1;    // GEMM2 row tile: pairs 4rg..4rg+3 (partners share)
    const int wc2 = w & 1;           // GEMM2 col block: 64wc2
    const int gr  = w >> 3;          // GEMM2 k-subrange within each tile: [16gr,16gr+16)
    const int bk  = gr * 16;
    const bool epi_w = (w < 8);      // epilogue/state owners
    const int row0 = blockIdx.x * TM;

    unsigned smem_base;
    asm("{ .reg .u64 t; cvta.to.shared.u64 t, %1; cvt.u32.u64 %0, t; }"
        : "=r"(smem_base) : "l"(smraw));
    const unsigned W2t_u = smem_base + 180224;

    // Stage W1 (coalesced float4).
    for (int i = tid; i < LATENTS * HIDDEN / 4; i += NTHR)
        ((float4*)W1s)[i] = ((const float4*)W1)[i];

    // t=0 output, fully coalesced.
    for (int i = tid; i < TM * LATENTS / 4; i += NTHR) {
        int r = i >> 5, c4 = i & 31;
        float4 v = ((const float4*)(fp + (size_t)(row0 + r) * LATENTS))[c4];
        ((float4*)(out + (size_t)(row0 + r) * TSTEPS * LATENTS))[c4] = v;
    }

    const ULL rb1lo = pack2(b1[64 * wc + 2 * tc]);
    const ULL rb1hi = pack2(b1[64 * wc + 2 * tc + 1]);
    const ULL ONE   = pack2(1.0f);

    ULL yb[4][2], acc[4][2], rb2[2];
    const int cb = 64 * wc2 + 2 * tc;
    rb2[0] = pack2(b2[cb]);
    rb2[1] = pack2(b2[cb + 1]);
    if (epi_w) {
        #pragma unroll
        for (int p = 0; p < 4; p++) {
            int r = row0 + 8 * rg + 2 * p;
            yb[p][0] = packab(fp[(size_t)r * LATENTS + cb],     fp[(size_t)(r + 1) * LATENTS + cb]);
            yb[p][1] = packab(fp[(size_t)r * LATENTS + cb + 1], fp[(size_t)(r + 1) * LATENTS + cb + 1]);
            ulonglong2 yy; yy.x = yb[p][0]; yy.y = yb[p][1];
            *(ulonglong2*)&Yp[(4 * rg + p) * LATENTS + cb] = yy;
        }
    }
    __syncthreads();

    for (int t = 0; t < TSTEPS - 1; t++) {
        float dt   = __ldg(&ts[t + 1]) - __ldg(&ts[t]);
        float half = 0.5f * dt;

        #pragma unroll 1
        for (int s = 0; s < 4; s++) {
            // All threads: async-commit tiles 0 and 1 (land during GEMM1).
            {
                const float* s0 = W2 + tid * 8;
                unsigned d0 = W2t_u + (unsigned)tid * 32;
                cp16(d0, s0); cp16(d0 + 16, s0 + 4);
                cp_commit();
                const float* s1 = s0 + 4096;
                unsigned d1 = d0 + 16384;
                cp16(d1, s1); cp16(d1 + 16, s1 + 4);
                cp_commit();
            }

            // ---------------- GEMM1 (all 16 warps, row-pair) ----------------
            ULL h[4][2];
            #pragma unroll
            for (int p = 0; p < 4; p++) { h[p][0] = rb1lo; h[p][1] = rb1hi; }
            {
                const float* w1c = &W1s[64 * wc + 2 * tc];
                const ULL*   yp0 = &Yp[(4 * wr + 0) * LATENTS];
                const ULL*   yp1 = &Yp[(4 * wr + 1) * LATENTS];
                const ULL*   yp2 = &Yp[(4 * wr + 2) * LATENTS];
                const ULL*   yp3 = &Yp[(4 * wr + 3) * LATENTS];
                #pragma unroll 2
                for (int k0 = 0; k0 < LATENTS; k0 += 2) {
                    ulonglong2 a0 = *(const ulonglong2*)&yp0[k0];
                    ulonglong2 a1 = *(const ulonglong2*)&yp1[k0];
                    ulonglong2 a2 = *(const ulonglong2*)&yp2[k0];
                    ulonglong2 a3 = *(const ulonglong2*)&yp3[k0];
                    ULL wv0 = *(const ULL*)&w1c[(k0    ) * HIDDEN];
                    ULL wv1 = *(const ULL*)&w1c[(k0 + 1) * HIDDEN];
                    float wl, wh;
                    unpack2(wv0, wl, wh);
                    { ULL bl = pack2(wl), bh = pack2(wh);
                      h[0][0] = ffma2(a0.x, bl, h[0][0]); h[0][1] = ffma2(a0.x, bh, h[0][1]);
                      h[1][0] = ffma2(a1.x, bl, h[1][0]); h[1][1] = ffma2(a1.x, bh, h[1][1]);
                      h[2][0] = ffma2(a2.x, bl, h[2][0]); h[2][1] = ffma2(a2.x, bh, h[2][1]);
                      h[3][0] = ffma2(a3.x, bl, h[3][0]); h[3][1] = ffma2(a3.x, bh, h[3][1]); }
                    unpack2(wv1, wl, wh);
                    { ULL bl = pack2(wl), bh = pack2(wh);
                      h[0][0] = ffma2(a0.y, bl, h[0][0]); h[0][1] = ffma2(a0.y, bh, h[0][1]);
                      h[1][0] = ffma2(a1.y, bl, h[1][0]); h[1][1] = ffma2(a1.y, bh, h[1][1]);
                      h[2][0] = ffma2(a2.y, bl, h[2][0]); h[2][1] = ffma2(a2.y, bh, h[2][1]);
                      h[3][0] = ffma2(a3.y, bl, h[3][0]); h[3][1] = ffma2(a3.y, bh, h[3][1]); }
                }
            }

            // tanh -> Zp (dense STS.128, conflict-free).
            #pragma unroll
            for (int p = 0; p < 4; p++) {
                float x0, x1, x2, x3;
                unpack2(h[p][0], x0, x1);
                unpack2(h[p][1], x2, x3);
                ulonglong2 zz;
                zz.x = packab(fast_tanh(x0), fast_tanh(x1));
                zz.y = packab(fast_tanh(x2), fast_tanh(x3));
                *(ulonglong2*)&Zp[(4 * wr + p) * HIDDEN + 64 * wc + 2 * tc] = zz;
            }
            __syncthreads();

            // ------- GEMM2 (ALL 16 warps; partners w,w+8 split kk of tile) --
            ULL o[4][2];
            if (gr == 0) {
                #pragma unroll
                for (int p = 0; p < 4; p++) { o[p][0] = rb2[0]; o[p][1] = rb2[1]; }
            } else {
                #pragma unroll
                for (int p = 0; p < 4; p++) { o[p][0] = 0ULL; o[p][1] = 0ULL; }
            }

            #pragma unroll 1
            for (int kt = 0; kt < 8; kt++) {
                cp_wait1();                        // tile kt landed (own copies)
                __syncthreads();                   // all threads' copies visible
                if (kt < 6) {
                    const float* src = W2 + (kt + 2) * 4096 + tid * 8;
                    unsigned dst = W2t_u + (unsigned)(((kt + 2) % 3) * 16384 + tid * 32);
                    cp16(dst, src); cp16(dst + 16, src + 4);
                    cp_commit();
                }
                {
                    const float* Wt = W2t + (kt % 3) * 4096 + cb;
                    const ULL* zb0 = &Zp[(4 * rg + 0) * HIDDEN + kt * 32];
                    const ULL* zb1 = &Zp[(4 * rg + 1) * HIDDEN + kt * 32];
                    const ULL* zb2 = &Zp[(4 * rg + 2) * HIDDEN + kt * 32];
                    const ULL* zb3 = &Zp[(4 * rg + 3) * HIDDEN + kt * 32];
                    #pragma unroll
                    for (int q = 0; q < 16; q += 2) {
                        const int kk0 = bk + q;
                        ulonglong2 z0 = *(const ulonglong2*)&zb0[kk0];
                        ulonglong2 z1 = *(const ulonglong2*)&zb1[kk0];
                        ulonglong2 z2 = *(const ulonglong2*)&zb2[kk0];
                        ulonglong2 z3 = *(const ulonglong2*)&zb3[kk0];
                        ULL wv0 = *(const ULL*)&Wt[(kk0    ) * LATENTS];
                        ULL wv1 = *(const ULL*)&Wt[(kk0 + 1) * LATENTS];
                        float wl, wh;
                        unpack2(wv0, wl, wh);
                        { ULL bl = pack2(wl), bh = pack2(wh);
                          o[0][0] = ffma2(z0.x, bl, o[0][0]); o[0][1] = ffma2(z0.x, bh, o[0][1]);
                          o[1][0] = ffma2(z1.x, bl, o[1][0]); o[1][1] = ffma2(z1.x, bh, o[1][1]);
                          o[2][0] = ffma2(z2.x, bl, o[2][0]); o[2][1] = ffma2(z2.x, bh, o[2][1]);
                          o[3][0] = ffma2(z3.x, bl, o[3][0]); o[3][1] = ffma2(z3.x, bh, o[3][1]); }
                        unpack2(wv1, wl, wh);
                        { ULL bl = pack2(wl), bh = pack2(wh);
                          o[0][0] = ffma2(z0.y, bl, o[0][0]); o[0][1] = ffma2(z0.y, bh, o[0][1]);
                          o[1][0] = ffma2(z1.y, bl, o[1][0]); o[1][1] = ffma2(z1.y, bh, o[1][1]);
                          o[2][0] = ffma2(z2.y, bl, o[2][0]); o[2][1] = ffma2(z2.y, bh, o[2][1]);
                          o[3][0] = ffma2(z3.y, bl, o[3][0]); o[3][1] = ffma2(z3.y, bh, o[3][1]); }
                    }
                }
            }

            // ------- partner reduction: group1 -> smem, group0 adds ---------
            __syncthreads();                       // buf0 free; partials ready
            if (gr == 1) {
                ULL* rd = &Red[((w - 8) * 32 + tc) * 8];
                #pragma unroll
                for (int p = 0; p < 4; p++) {
                    ulonglong2 v; v.x = o[p][0]; v.y = o[p][1];
                    *(ulonglong2*)&rd[2 * p] = v;
                }
            }
            __syncthreads();
            if (gr == 0) {
                const ULL* rd = &Red[(w * 32 + tc) * 8];
                #pragma unroll
                for (int p = 0; p < 4; p++) {
                    ulonglong2 v = *(const ulonglong2*)&rd[2 * p];
                    o[p][0] = ffma2(ONE, v.x, o[p][0]);
                    o[p][1] = ffma2(ONE, v.y, o[p][1]);
                }
            }

            // ---------------- RK4 epilogue (packed, warps 0-7) --------------
            if (epi_w) {
                if (s == 0) {
                    #pragma unroll
                    for (int p = 0; p < 4; p++) { acc[p][0] = o[p][0]; acc[p][1] = o[p][1]; }
                } else {
                    ULL cwv = pack2((s == 3) ? 1.0f : 2.0f);
                    #pragma unroll
                    for (int p = 0; p < 4; p++) {
                        acc[p][0] = ffma2(cwv, o[p][0], acc[p][0]);
                        acc[p][1] = ffma2(cwv, o[p][1], acc[p][1]);
                    }
                }
                if (s < 3) {
                    ULL ewv = pack2((s < 2) ? half : dt);
                    #pragma unroll
                    for (int p = 0; p < 4; p++) {
                        ulonglong2 yy;
                        yy.x = ffma2(ewv, o[p][0], yb[p][0]);
                        yy.y = ffma2(ewv, o[p][1], yb[p][1]);
                        *(ulonglong2*)&Yp[(4 * rg + p) * LATENTS + cb] = yy;
                    }
                } else {
                    ULL c6 = pack2(dt * (1.0f / 6.0f));
                    #pragma unroll
                    for (int p = 0; p < 4; p++) {
                        yb[p][0] = ffma2(c6, acc[p][0], yb[p][0]);
                        yb[p][1] = ffma2(c6, acc[p][1], yb[p][1]);
                        ulonglong2 yy; yy.x = yb[p][0]; yy.y = yb[p][1];
                        *(ulonglong2*)&Yp[(4 * rg + p) * LATENTS + cb] = yy;
                        int r = row0 + 8 * rg + 2 * p;
                        float lo, hi;
                        size_t base0 = ((size_t)r * TSTEPS + (t + 1)) * LATENTS + cb;
                        size_t base1 = ((size_t)(r + 1) * TSTEPS + (t + 1)) * LATENTS + cb;
                        unpack2(yb[p][0], lo, hi);
                        out[base0] = lo;     out[base1] = hi;
                        unpack2(yb[p][1], lo, hi);
                        out[base0 + 1] = lo; out[base1 + 1] = hi;
                    }
                }
            }
            __syncthreads();
        }
    }
}

extern "C" void kernel_launch(void* const* d_in, const int* in_sizes, int n_in,
                              void* d_out, int out_size) {
    const float* fp = (const float*)d_in[0];
    const float* ts = (const float*)d_in[1];
    const float* W1 = (const float*)d_in[2];
    const float* b1 = (const float*)d_in[3];
    const float* W2 = (const float*)d_in[4];
    const float* b2 = (const float*)d_in[5];
    float* out = (float*)d_out;

    cudaFuncSetAttribute(ode_rk4_kernel,
                         cudaFuncAttributeMaxDynamicSharedMemorySize, SM_BYTES);
    ode_rk4_kernel<<<NROWS / TM, NTHR, SM_BYTES>>>(fp, ts, W1, b1, W2, b2, out);
}